// round 1
// baseline (speedup 1.0000x reference)
#include <cuda_runtime.h>
#include <math.h>

#define BATCH 16
#define SEQ   2048
#define DIM   512
#define EMB   512

// Scratch for projected q/k/v (allocation-free rule: __device__ globals)
__device__ float g_qp[BATCH * SEQ * EMB];
__device__ float g_kp[BATCH * SEQ * EMB];
__device__ float g_vp[BATCH * SEQ * EMB];

// ---------------------------------------------------------------------------
// NT GEMM: C[M,Nn] = alpha * A[M,K] @ B[Nn,K]^T     (both operands K-major)
// 128x128 tile, BK=8, 256 threads, 8x8 per thread.
// ---------------------------------------------------------------------------
__global__ void __launch_bounds__(256) gemm_nt(
    const float* __restrict__ A, const float* __restrict__ Bm,
    float* __restrict__ C, int M, int Nn, int K, float alpha,
    long sA, long sB, long sC)
{
    A  += (long)blockIdx.z * sA;
    Bm += (long)blockIdx.z * sB;
    C  += (long)blockIdx.z * sC;

    __shared__ float As[8][132];
    __shared__ float Bs[8][132];

    const int tid = threadIdx.x;
    const int tx = tid & 15;         // 0..15 -> col group
    const int ty = tid >> 4;         // 0..15 -> row group
    const int rowBase = blockIdx.y * 128;
    const int colBase = blockIdx.x * 128;

    // loaders: 256 threads * float4 = 1024 floats = 128 rows x 8 k
    const int lrow = tid >> 1;       // 0..127
    const int lk   = (tid & 1) * 4;  // 0 or 4

    const float* Aptr = A  + (long)(rowBase + lrow) * K + lk;
    const float* Bptr = Bm + (long)(colBase + lrow) * K + lk;

    float acc[8][8];
#pragma unroll
    for (int i = 0; i < 8; i++)
#pragma unroll
        for (int j = 0; j < 8; j++) acc[i][j] = 0.f;

    for (int k0 = 0; k0 < K; k0 += 8) {
        float4 a4 = *(const float4*)(Aptr + k0);
        float4 b4 = *(const float4*)(Bptr + k0);
        As[lk + 0][lrow] = a4.x; As[lk + 1][lrow] = a4.y;
        As[lk + 2][lrow] = a4.z; As[lk + 3][lrow] = a4.w;
        Bs[lk + 0][lrow] = b4.x; Bs[lk + 1][lrow] = b4.y;
        Bs[lk + 2][lrow] = b4.z; Bs[lk + 3][lrow] = b4.w;
        __syncthreads();

#pragma unroll
        for (int kk = 0; kk < 8; kk++) {
            float4 a0 = *(const float4*)&As[kk][ty * 8];
            float4 a1 = *(const float4*)&As[kk][ty * 8 + 4];
            float4 b0 = *(const float4*)&Bs[kk][tx * 8];
            float4 b1 = *(const float4*)&Bs[kk][tx * 8 + 4];
            float ar[8] = {a0.x, a0.y, a0.z, a0.w, a1.x, a1.y, a1.z, a1.w};
            float br[8] = {b0.x, b0.y, b0.z, b0.w, b1.x, b1.y, b1.z, b1.w};
#pragma unroll
            for (int i = 0; i < 8; i++)
#pragma unroll
                for (int j = 0; j < 8; j++)
                    acc[i][j] = fmaf(ar[i], br[j], acc[i][j]);
        }
        __syncthreads();
    }

#pragma unroll
    for (int i = 0; i < 8; i++) {
        float* cp = C + (long)(rowBase + ty * 8 + i) * Nn + colBase + tx * 8;
        float4 v0 = make_float4(acc[i][0] * alpha, acc[i][1] * alpha,
                                acc[i][2] * alpha, acc[i][3] * alpha);
        float4 v1 = make_float4(acc[i][4] * alpha, acc[i][5] * alpha,
                                acc[i][6] * alpha, acc[i][7] * alpha);
        *(float4*)cp       = v0;
        *(float4*)(cp + 4) = v1;
    }
}

// ---------------------------------------------------------------------------
// NN GEMM: C[M,Nn] = alpha * A[M,K] @ B[K,Nn]       (B row-major, Nn-major)
// ---------------------------------------------------------------------------
__global__ void __launch_bounds__(256) gemm_nn(
    const float* __restrict__ A, const float* __restrict__ Bm,
    float* __restrict__ C, int M, int Nn, int K, float alpha,
    long sA, long sB, long sC)
{
    A  += (long)blockIdx.z * sA;
    Bm += (long)blockIdx.z * sB;
    C  += (long)blockIdx.z * sC;

    __shared__ float As[8][132];
    __shared__ float Bs[8][132];

    const int tid = threadIdx.x;
    const int tx = tid & 15;
    const int ty = tid >> 4;
    const int rowBase = blockIdx.y * 128;
    const int colBase = blockIdx.x * 128;

    // A loader (K-major): same as NT
    const int lrow = tid >> 1;
    const int lk   = (tid & 1) * 4;
    // B loader (Nn-major): 8 k-rows x 128 cols, float4 along n
    const int lbk = tid >> 5;          // 0..7
    const int lbn = (tid & 31) * 4;    // 0..124

    const float* Aptr = A  + (long)(rowBase + lrow) * K + lk;
    const float* Bptr = Bm + (long)lbk * Nn + colBase + lbn;

    float acc[8][8];
#pragma unroll
    for (int i = 0; i < 8; i++)
#pragma unroll
        for (int j = 0; j < 8; j++) acc[i][j] = 0.f;

    for (int k0 = 0; k0 < K; k0 += 8) {
        float4 a4 = *(const float4*)(Aptr + k0);
        float4 b4 = *(const float4*)(Bptr + (long)k0 * Nn);
        As[lk + 0][lrow] = a4.x; As[lk + 1][lrow] = a4.y;
        As[lk + 2][lrow] = a4.z; As[lk + 3][lrow] = a4.w;
        *(float4*)&Bs[lbk][lbn] = b4;
        __syncthreads();

#pragma unroll
        for (int kk = 0; kk < 8; kk++) {
            float4 a0 = *(const float4*)&As[kk][ty * 8];
            float4 a1 = *(const float4*)&As[kk][ty * 8 + 4];
            float4 b0 = *(const float4*)&Bs[kk][tx * 8];
            float4 b1 = *(const float4*)&Bs[kk][tx * 8 + 4];
            float ar[8] = {a0.x, a0.y, a0.z, a0.w, a1.x, a1.y, a1.z, a1.w};
            float br[8] = {b0.x, b0.y, b0.z, b0.w, b1.x, b1.y, b1.z, b1.w};
#pragma unroll
            for (int i = 0; i < 8; i++)
#pragma unroll
                for (int j = 0; j < 8; j++)
                    acc[i][j] = fmaf(ar[i], br[j], acc[i][j]);
        }
        __syncthreads();
    }

#pragma unroll
    for (int i = 0; i < 8; i++) {
        float* cp = C + (long)(rowBase + ty * 8 + i) * Nn + colBase + tx * 8;
        float4 v0 = make_float4(acc[i][0] * alpha, acc[i][1] * alpha,
                                acc[i][2] * alpha, acc[i][3] * alpha);
        float4 v1 = make_float4(acc[i][4] * alpha, acc[i][5] * alpha,
                                acc[i][6] * alpha, acc[i][7] * alpha);
        *(float4*)cp       = v0;
        *(float4*)(cp + 4) = v1;
    }
}

// ---------------------------------------------------------------------------
// Row softmax (in place): one block per row of SEQ elements, 256 threads x 8.
// ---------------------------------------------------------------------------
__global__ void __launch_bounds__(256) softmax_rows(float* __restrict__ attn)
{
    float* p = attn + (long)blockIdx.x * SEQ;
    const int tid = threadIdx.x;
    __shared__ float red[256];

    float vals[8];
    float lmax = -INFINITY;
#pragma unroll
    for (int i = 0; i < 8; i++) {
        vals[i] = p[tid + i * 256];
        lmax = fmaxf(lmax, vals[i]);
    }
    red[tid] = lmax;
    __syncthreads();
    for (int s = 128; s > 0; s >>= 1) {
        if (tid < s) red[tid] = fmaxf(red[tid], red[tid + s]);
        __syncthreads();
    }
    const float m = red[0];
    __syncthreads();

    float lsum = 0.f;
#pragma unroll
    for (int i = 0; i < 8; i++) {
        vals[i] = expf(vals[i] - m);
        lsum += vals[i];
    }
    red[tid] = lsum;
    __syncthreads();
    for (int s = 128; s > 0; s >>= 1) {
        if (tid < s) red[tid] += red[tid + s];
        __syncthreads();
    }
    const float inv = 1.f / red[0];
#pragma unroll
    for (int i = 0; i < 8; i++)
        p[tid + i * 256] = vals[i] * inv;
}

// ---------------------------------------------------------------------------
extern "C" void kernel_launch(void* const* d_in, const int* in_sizes, int n_in,
                              void* d_out, int out_size)
{
    const float* q  = (const float*)d_in[0];
    const float* k  = (const float*)d_in[1];
    const float* v  = (const float*)d_in[2];
    const float* Wq = (const float*)d_in[3];
    const float* Wk = (const float*)d_in[4];
    const float* Wv = (const float*)d_in[5];

    float* out  = (float*)d_out;                          // [B, N, E]
    float* attn = out + (long)BATCH * SEQ * EMB;          // [B, N, N]

    float *qp, *kp, *vp;
    cudaGetSymbolAddress((void**)&qp, g_qp);
    cudaGetSymbolAddress((void**)&kp, g_kp);
    cudaGetSymbolAddress((void**)&vp, g_vp);

    const float c = 0.044194173824159216f;  // 1/sqrt(512), both LR-equalizer and attn scale

    // Projections: fold batch into M (q/k/v are [B*N, D] contiguous)
    dim3 gp(EMB / 128, (BATCH * SEQ) / 128, 1);
    gemm_nt<<<gp, 256>>>(q, Wq, qp, BATCH * SEQ, EMB, DIM, c, 0, 0, 0);
    gemm_nt<<<gp, 256>>>(k, Wk, kp, BATCH * SEQ, EMB, DIM, c, 0, 0, 0);
    gemm_nt<<<gp, 256>>>(v, Wv, vp, BATCH * SEQ, EMB, DIM, c, 0, 0, 0);

    // dots = qp @ kp^T * E^-0.5 -> written straight into attn output region
    dim3 gd(SEQ / 128, SEQ / 128, BATCH);
    gemm_nt<<<gd, 256>>>(qp, kp, attn, SEQ, SEQ, EMB, c,
                         (long)SEQ * EMB, (long)SEQ * EMB, (long)SEQ * SEQ);

    // softmax in place over last dim
    softmax_rows<<<BATCH * SEQ, 256>>>(attn);

    // out = attn @ vp
    dim3 go(EMB / 128, SEQ / 128, BATCH);
    gemm_nn<<<go, 256>>>(attn, vp, out, SEQ, EMB, SEQ, 1.0f,
                         (long)SEQ * SEQ, (long)SEQ * EMB, (long)SEQ * EMB);
}

// round 2
// speedup vs baseline: 1.5987x; 1.5987x over previous
#include <cuda_runtime.h>
#include <math.h>

#define BATCH 16
#define SEQ   2048
#define DIM   512
#define EMB   512

__device__ float g_qp[BATCH * SEQ * EMB];
__device__ float g_kp[BATCH * SEQ * EMB];
__device__ float g_vp[BATCH * SEQ * EMB];

// ---------------------------------------------------------------------------
// tf32 split: x ~= hi + lo, both tf32-rounded. 3 mmas (hh, hl, lh) give ~fp32.
// ---------------------------------------------------------------------------
__device__ __forceinline__ float2 tf32_split(float x)
{
    unsigned u;
    asm("cvt.rna.tf32.f32 %0, %1;" : "=r"(u) : "f"(x));
    float hi = __uint_as_float(u);
    float lo = x - hi;
    unsigned v;
    asm("cvt.rna.tf32.f32 %0, %1;" : "=r"(v) : "f"(lo));
    return make_float2(hi, __uint_as_float(v));
}

__device__ __forceinline__ void mma_tf32(float* d,
    unsigned a0, unsigned a1, unsigned a2, unsigned a3,
    unsigned b0, unsigned b1)
{
    asm volatile(
        "mma.sync.aligned.m16n8k8.row.col.f32.tf32.tf32.f32 "
        "{%0,%1,%2,%3}, {%4,%5,%6,%7}, {%8,%9}, {%0,%1,%2,%3};"
        : "+f"(d[0]), "+f"(d[1]), "+f"(d[2]), "+f"(d[3])
        : "r"(a0), "r"(a1), "r"(a2), "r"(a3), "r"(b0), "r"(b1));
}

// interleaved k-position within a 16-wide stage: pairs (t, t+4) adjacent
// k in [0,16): block = k/8, j = k%8 ; p = block*8 + (j<4 ? 2*j : 2*(j-4)+1)

#define SROW 20  // padded row stride (words), 16 used

// ---------------------------------------------------------------------------
// NT: C[M,N] = alpha * A[M,K] @ B[N,K]^T   (both K-major), tensor cores
// 128x128 tile, BK=16, 256 threads (8 warps: 2 row x 4 col, 64x32 each)
// ---------------------------------------------------------------------------
__global__ void __launch_bounds__(256) gemm_nt_tc(
    const float* __restrict__ A, const float* __restrict__ Bm,
    float* __restrict__ C, int M, int Nn, int K, float alpha,
    long sA, long sB, long sC)
{
    A  += (long)blockIdx.z * sA;
    Bm += (long)blockIdx.z * sB;
    C  += (long)blockIdx.z * sC;

    __shared__ float As[2][128][SROW];   // [hi/lo][row][k-perm]
    __shared__ float Bs[2][128][SROW];

    const int tid  = threadIdx.x;
    const int lane = tid & 31;
    const int warp = tid >> 5;
    const int gid  = lane >> 2;   // 0..7
    const int tig  = lane & 3;    // 0..3
    const int wr   = warp & 1;    // warp row (2)
    const int wc   = warp >> 1;   // warp col (4)

    const int rowBase = blockIdx.y * 128;
    const int colBase = blockIdx.x * 128;

    // loaders: 256 threads, each handles 8 consecutive k of one row
    const int lrow = tid >> 1;          // 0..127
    const int lk0  = (tid & 1) * 8;     // 0 or 8

    const float* Aptr = A  + (long)(rowBase + lrow) * K + lk0;
    const float* Bptr = Bm + (long)(colBase + lrow) * K + lk0;

    float acc[4][4][4];
#pragma unroll
    for (int i = 0; i < 4; i++)
#pragma unroll
        for (int j = 0; j < 4; j++)
#pragma unroll
            for (int r = 0; r < 4; r++) acc[i][j][r] = 0.f;

    for (int k0 = 0; k0 < K; k0 += 16) {
        float4 av0 = *(const float4*)(Aptr + k0);
        float4 av1 = *(const float4*)(Aptr + k0 + 4);
        float4 bv0 = *(const float4*)(Bptr + k0);
        float4 bv1 = *(const float4*)(Bptr + k0 + 4);
        {
            float2 s;
            s = tf32_split(av0.x); As[0][lrow][lk0+0] = s.x; As[1][lrow][lk0+0] = s.y;
            s = tf32_split(av0.y); As[0][lrow][lk0+2] = s.x; As[1][lrow][lk0+2] = s.y;
            s = tf32_split(av0.z); As[0][lrow][lk0+4] = s.x; As[1][lrow][lk0+4] = s.y;
            s = tf32_split(av0.w); As[0][lrow][lk0+6] = s.x; As[1][lrow][lk0+6] = s.y;
            s = tf32_split(av1.x); As[0][lrow][lk0+1] = s.x; As[1][lrow][lk0+1] = s.y;
            s = tf32_split(av1.y); As[0][lrow][lk0+3] = s.x; As[1][lrow][lk0+3] = s.y;
            s = tf32_split(av1.z); As[0][lrow][lk0+5] = s.x; As[1][lrow][lk0+5] = s.y;
            s = tf32_split(av1.w); As[0][lrow][lk0+7] = s.x; As[1][lrow][lk0+7] = s.y;
            s = tf32_split(bv0.x); Bs[0][lrow][lk0+0] = s.x; Bs[1][lrow][lk0+0] = s.y;
            s = tf32_split(bv0.y); Bs[0][lrow][lk0+2] = s.x; Bs[1][lrow][lk0+2] = s.y;
            s = tf32_split(bv0.z); Bs[0][lrow][lk0+4] = s.x; Bs[1][lrow][lk0+4] = s.y;
            s = tf32_split(bv0.w); Bs[0][lrow][lk0+6] = s.x; Bs[1][lrow][lk0+6] = s.y;
            s = tf32_split(bv1.x); Bs[0][lrow][lk0+1] = s.x; Bs[1][lrow][lk0+1] = s.y;
            s = tf32_split(bv1.y); Bs[0][lrow][lk0+3] = s.x; Bs[1][lrow][lk0+3] = s.y;
            s = tf32_split(bv1.z); Bs[0][lrow][lk0+5] = s.x; Bs[1][lrow][lk0+5] = s.y;
            s = tf32_split(bv1.w); Bs[0][lrow][lk0+7] = s.x; Bs[1][lrow][lk0+7] = s.y;
        }
        __syncthreads();

#pragma unroll
        for (int kk = 0; kk < 16; kk += 8) {
            // A fragments: [mi][hi/lo][4 regs]
            unsigned af[4][2][4];
#pragma unroll
            for (int mi = 0; mi < 4; mi++) {
                int r0 = wr * 64 + mi * 16 + gid;
#pragma unroll
                for (int h = 0; h < 2; h++) {
                    float2 u = *(const float2*)&As[h][r0][kk + 2 * tig];
                    float2 w = *(const float2*)&As[h][r0 + 8][kk + 2 * tig];
                    af[mi][h][0] = __float_as_uint(u.x);  // (g, t)
                    af[mi][h][1] = __float_as_uint(w.x);  // (g+8, t)
                    af[mi][h][2] = __float_as_uint(u.y);  // (g, t+4)
                    af[mi][h][3] = __float_as_uint(w.y);  // (g+8, t+4)
                }
            }
            unsigned bf[4][2][2];
#pragma unroll
            for (int ni = 0; ni < 4; ni++) {
                int c0 = wc * 32 + ni * 8 + gid;
#pragma unroll
                for (int h = 0; h < 2; h++) {
                    float2 u = *(const float2*)&Bs[h][c0][kk + 2 * tig];
                    bf[ni][h][0] = __float_as_uint(u.x);  // (t, g)
                    bf[ni][h][1] = __float_as_uint(u.y);  // (t+4, g)
                }
            }
#pragma unroll
            for (int mi = 0; mi < 4; mi++)
#pragma unroll
                for (int ni = 0; ni < 4; ni++) {
                    float* d = acc[mi][ni];
                    mma_tf32(d, af[mi][0][0], af[mi][0][1], af[mi][0][2], af[mi][0][3],
                                bf[ni][0][0], bf[ni][0][1]);
                    mma_tf32(d, af[mi][0][0], af[mi][0][1], af[mi][0][2], af[mi][0][3],
                                bf[ni][1][0], bf[ni][1][1]);
                    mma_tf32(d, af[mi][1][0], af[mi][1][1], af[mi][1][2], af[mi][1][3],
                                bf[ni][0][0], bf[ni][0][1]);
                }
        }
        __syncthreads();
    }

#pragma unroll
    for (int mi = 0; mi < 4; mi++) {
        int r = rowBase + wr * 64 + mi * 16 + gid;
#pragma unroll
        for (int ni = 0; ni < 4; ni++) {
            int cc = colBase + wc * 32 + ni * 8 + 2 * tig;
            float2 v0 = make_float2(acc[mi][ni][0] * alpha, acc[mi][ni][1] * alpha);
            float2 v1 = make_float2(acc[mi][ni][2] * alpha, acc[mi][ni][3] * alpha);
            *(float2*)(C + (long)r * Nn + cc)       = v0;
            *(float2*)(C + (long)(r + 8) * Nn + cc) = v1;
        }
    }
}

// ---------------------------------------------------------------------------
// NN: C[M,N] = alpha * A[M,K] @ B[K,N]   (B n-major), tensor cores
// ---------------------------------------------------------------------------
__global__ void __launch_bounds__(256) gemm_nn_tc(
    const float* __restrict__ A, const float* __restrict__ Bm,
    float* __restrict__ C, int M, int Nn, int K, float alpha,
    long sA, long sB, long sC)
{
    A  += (long)blockIdx.z * sA;
    Bm += (long)blockIdx.z * sB;
    C  += (long)blockIdx.z * sC;

    __shared__ float As[2][128][SROW];
    __shared__ float Bs[2][16][132];   // [hi/lo][k][n]

    const int tid  = threadIdx.x;
    const int lane = tid & 31;
    const int warp = tid >> 5;
    const int gid  = lane >> 2;
    const int tig  = lane & 3;
    const int wr   = warp & 1;
    const int wc   = warp >> 1;

    const int rowBase = blockIdx.y * 128;
    const int colBase = blockIdx.x * 128;

    const int lrow = tid >> 1;
    const int lk0  = (tid & 1) * 8;
    const int bkr  = tid >> 4;          // 0..15
    const int bn0  = (tid & 15) * 8;    // 0..120

    const float* Aptr = A  + (long)(rowBase + lrow) * K + lk0;
    const float* Bptr = Bm + (long)bkr * Nn + colBase + bn0;

    float acc[4][4][4];
#pragma unroll
    for (int i = 0; i < 4; i++)
#pragma unroll
        for (int j = 0; j < 4; j++)
#pragma unroll
            for (int r = 0; r < 4; r++) acc[i][j][r] = 0.f;

    for (int k0 = 0; k0 < K; k0 += 16) {
        float4 av0 = *(const float4*)(Aptr + k0);
        float4 av1 = *(const float4*)(Aptr + k0 + 4);
        float4 bv0 = *(const float4*)(Bptr + (long)k0 * Nn);
        float4 bv1 = *(const float4*)(Bptr + (long)k0 * Nn + 4);
        {
            float2 s;
            s = tf32_split(av0.x); As[0][lrow][lk0+0] = s.x; As[1][lrow][lk0+0] = s.y;
            s = tf32_split(av0.y); As[0][lrow][lk0+2] = s.x; As[1][lrow][lk0+2] = s.y;
            s = tf32_split(av0.z); As[0][lrow][lk0+4] = s.x; As[1][lrow][lk0+4] = s.y;
            s = tf32_split(av0.w); As[0][lrow][lk0+6] = s.x; As[1][lrow][lk0+6] = s.y;
            s = tf32_split(av1.x); As[0][lrow][lk0+1] = s.x; As[1][lrow][lk0+1] = s.y;
            s = tf32_split(av1.y); As[0][lrow][lk0+3] = s.x; As[1][lrow][lk0+3] = s.y;
            s = tf32_split(av1.z); As[0][lrow][lk0+5] = s.x; As[1][lrow][lk0+5] = s.y;
            s = tf32_split(av1.w); As[0][lrow][lk0+7] = s.x; As[1][lrow][lk0+7] = s.y;

            float4 h4, l4; float2 t;
            t = tf32_split(bv0.x); h4.x = t.x; l4.x = t.y;
            t = tf32_split(bv0.y); h4.y = t.x; l4.y = t.y;
            t = tf32_split(bv0.z); h4.z = t.x; l4.z = t.y;
            t = tf32_split(bv0.w); h4.w = t.x; l4.w = t.y;
            *(float4*)&Bs[0][bkr][bn0] = h4;
            *(float4*)&Bs[1][bkr][bn0] = l4;
            t = tf32_split(bv1.x); h4.x = t.x; l4.x = t.y;
            t = tf32_split(bv1.y); h4.y = t.x; l4.y = t.y;
            t = tf32_split(bv1.z); h4.z = t.x; l4.z = t.y;
            t = tf32_split(bv1.w); h4.w = t.x; l4.w = t.y;
            *(float4*)&Bs[0][bkr][bn0 + 4] = h4;
            *(float4*)&Bs[1][bkr][bn0 + 4] = l4;
        }
        __syncthreads();

#pragma unroll
        for (int kk = 0; kk < 16; kk += 8) {
            unsigned af[4][2][4];
#pragma unroll
            for (int mi = 0; mi < 4; mi++) {
                int r0 = wr * 64 + mi * 16 + gid;
#pragma unroll
                for (int h = 0; h < 2; h++) {
                    float2 u = *(const float2*)&As[h][r0][kk + 2 * tig];
                    float2 w = *(const float2*)&As[h][r0 + 8][kk + 2 * tig];
                    af[mi][h][0] = __float_as_uint(u.x);
                    af[mi][h][1] = __float_as_uint(w.x);
                    af[mi][h][2] = __float_as_uint(u.y);
                    af[mi][h][3] = __float_as_uint(w.y);
                }
            }
            unsigned bf[4][2][2];
#pragma unroll
            for (int ni = 0; ni < 4; ni++) {
                int c0 = wc * 32 + ni * 8 + gid;
#pragma unroll
                for (int h = 0; h < 2; h++) {
                    bf[ni][h][0] = __float_as_uint(Bs[h][kk + tig][c0]);
                    bf[ni][h][1] = __float_as_uint(Bs[h][kk + tig + 4][c0]);
                }
            }
#pragma unroll
            for (int mi = 0; mi < 4; mi++)
#pragma unroll
                for (int ni = 0; ni < 4; ni++) {
                    float* d = acc[mi][ni];
                    mma_tf32(d, af[mi][0][0], af[mi][0][1], af[mi][0][2], af[mi][0][3],
                                bf[ni][0][0], bf[ni][0][1]);
                    mma_tf32(d, af[mi][0][0], af[mi][0][1], af[mi][0][2], af[mi][0][3],
                                bf[ni][1][0], bf[ni][1][1]);
                    mma_tf32(d, af[mi][1][0], af[mi][1][1], af[mi][1][2], af[mi][1][3],
                                bf[ni][0][0], bf[ni][0][1]);
                }
        }
        __syncthreads();
    }

#pragma unroll
    for (int mi = 0; mi < 4; mi++) {
        int r = rowBase + wr * 64 + mi * 16 + gid;
#pragma unroll
        for (int ni = 0; ni < 4; ni++) {
            int cc = colBase + wc * 32 + ni * 8 + 2 * tig;
            float2 v0 = make_float2(acc[mi][ni][0] * alpha, acc[mi][ni][1] * alpha);
            float2 v1 = make_float2(acc[mi][ni][2] * alpha, acc[mi][ni][3] * alpha);
            *(float2*)(C + (long)r * Nn + cc)       = v0;
            *(float2*)(C + (long)(r + 8) * Nn + cc) = v1;
        }
    }
}

// ---------------------------------------------------------------------------
// Row softmax (in place)
// ---------------------------------------------------------------------------
__global__ void __launch_bounds__(256) softmax_rows(float* __restrict__ attn)
{
    float* p = attn + (long)blockIdx.x * SEQ;
    const int tid = threadIdx.x;
    __shared__ float red[256];

    float vals[8];
    float lmax = -INFINITY;
#pragma unroll
    for (int i = 0; i < 8; i++) {
        vals[i] = p[tid + i * 256];
        lmax = fmaxf(lmax, vals[i]);
    }
    red[tid] = lmax;
    __syncthreads();
    for (int s = 128; s > 0; s >>= 1) {
        if (tid < s) red[tid] = fmaxf(red[tid], red[tid + s]);
        __syncthreads();
    }
    const float m = red[0];
    __syncthreads();

    float lsum = 0.f;
#pragma unroll
    for (int i = 0; i < 8; i++) {
        vals[i] = expf(vals[i] - m);
        lsum += vals[i];
    }
    red[tid] = lsum;
    __syncthreads();
    for (int s = 128; s > 0; s >>= 1) {
        if (tid < s) red[tid] += red[tid + s];
        __syncthreads();
    }
    const float inv = 1.f / red[0];
#pragma unroll
    for (int i = 0; i < 8; i++)
        p[tid + i * 256] = vals[i] * inv;
}

// ---------------------------------------------------------------------------
extern "C" void kernel_launch(void* const* d_in, const int* in_sizes, int n_in,
                              void* d_out, int out_size)
{
    const float* q  = (const float*)d_in[0];
    const float* k  = (const float*)d_in[1];
    const float* v  = (const float*)d_in[2];
    const float* Wq = (const float*)d_in[3];
    const float* Wk = (const float*)d_in[4];
    const float* Wv = (const float*)d_in[5];

    float* out  = (float*)d_out;                  // [B, N, E]
    float* attn = out + (long)BATCH * SEQ * EMB;  // [B, N, N]

    float *qp, *kp, *vp;
    cudaGetSymbolAddress((void**)&qp, g_qp);
    cudaGetSymbolAddress((void**)&kp, g_kp);
    cudaGetSymbolAddress((void**)&vp, g_vp);

    const float c = 0.044194173824159216f;  // 1/sqrt(512)

    dim3 gp(EMB / 128, (BATCH * SEQ) / 128, 1);
    gemm_nt_tc<<<gp, 256>>>(q, Wq, qp, BATCH * SEQ, EMB, DIM, c, 0, 0, 0);
    gemm_nt_tc<<<gp, 256>>>(k, Wk, kp, BATCH * SEQ, EMB, DIM, c, 0, 0, 0);
    gemm_nt_tc<<<gp, 256>>>(v, Wv, vp, BATCH * SEQ, EMB, DIM, c, 0, 0, 0);

    dim3 gd(SEQ / 128, SEQ / 128, BATCH);
    gemm_nt_tc<<<gd, 256>>>(qp, kp, attn, SEQ, SEQ, EMB, c,
                            (long)SEQ * EMB, (long)SEQ * EMB, (long)SEQ * SEQ);

    softmax_rows<<<BATCH * SEQ, 256>>>(attn);

    dim3 go(EMB / 128, SEQ / 128, BATCH);
    gemm_nn_tc<<<go, 256>>>(attn, vp, out, SEQ, EMB, SEQ, 1.0f,
                            (long)SEQ * SEQ, (long)SEQ * EMB, (long)SEQ * EMB);
}

// round 4
// speedup vs baseline: 2.6231x; 1.6407x over previous
#include <cuda_runtime.h>
#include <cuda_bf16.h>
#include <math.h>
#include <stdint.h>

#define BATCH 16
#define SEQ   2048
#define DIM   512
#define EMB   512

__device__ float g_qp[BATCH * SEQ * EMB];
__device__ float g_kp[BATCH * SEQ * EMB];
__device__ float g_vp[BATCH * SEQ * EMB];
__device__ float g_vpt[BATCH * EMB * SEQ];

// ---------------------------------------------------------------------------
// bf16 split helpers: x = hi + lo (+ ~2^-17 residual), packed as bf16x2 words
// ---------------------------------------------------------------------------
__device__ __forceinline__ uint32_t pack2bf(float e0, float e1) {
    uint32_t r;
    asm("cvt.rn.bf16x2.f32 %0, %1, %2;" : "=r"(r) : "f"(e1), "f"(e0));
    return r;
}

__device__ __forceinline__ void split_pair(float x0, float x1,
                                           uint32_t& wh, uint32_t& wl) {
    wh = pack2bf(x0, x1);
    float h0 = __uint_as_float(wh << 16);
    float h1 = __uint_as_float(wh & 0xFFFF0000u);
    wl = pack2bf(x0 - h0, x1 - h1);
}

__device__ __forceinline__ void mma_bf16(float* d, const uint32_t* a,
                                         const uint32_t* b) {
    asm volatile(
        "mma.sync.aligned.m16n8k16.row.col.f32.bf16.bf16.f32 "
        "{%0,%1,%2,%3},{%4,%5,%6,%7},{%8,%9},{%0,%1,%2,%3};"
        : "+f"(d[0]), "+f"(d[1]), "+f"(d[2]), "+f"(d[3])
        : "r"(a[0]), "r"(a[1]), "r"(a[2]), "r"(a[3]), "r"(b[0]), "r"(b[1]));
}

// ---------------------------------------------------------------------------
// smem stage layout (words = uint32 bf16-pairs), per 128x128 CTA tile, BK=32:
//   A_hi[128][20] | A_lo[128][20] | B_hi[128][20] | B_lo[128][20]
// word positions within a row (16 used): interleaved so pos 8*kk + 2t   holds
// k8-chunk0 word t and pos 8*kk + 2t+1 holds chunk1 word t  (kk = k16 step).
// ---------------------------------------------------------------------------
#define SROW     20
#define PLANE_W  (128 * SROW)          // 2560 words per plane
#define STAGE_W  (4 * PLANE_W)         // 10240 words per stage
#define SMEM_BYTES (2 * STAGE_W * 4)   // 81920 bytes, double buffered

// NT GEMM: C[M,N] = alpha * A[M,K] @ B[N,K]^T  (both K-major)
// 128x128 CTA tile, 256 threads = 8 warps (2 row x 4 col), 64x32 warp tiles,
// bf16 3-split mma, BK=32, double-buffered.
__global__ void __launch_bounds__(256) gemm_bf3(
    const float* __restrict__ A, const float* __restrict__ Bm,
    float* __restrict__ C, int M, int Nn, int K, float alpha,
    long sA, long sB, long sC)
{
    extern __shared__ uint32_t sm[];

    const int tid  = threadIdx.x;
    const int lane = tid & 31;
    const int warp = tid >> 5;
    const int gid  = lane >> 2;    // 0..7
    const int tig  = lane & 3;     // 0..3
    const int wr   = warp & 1;     // 2 warp-rows
    const int wc   = warp >> 1;    // 4 warp-cols

    A  += (long)blockIdx.z * sA;
    Bm += (long)blockIdx.z * sB;
    C  += (long)blockIdx.z * sC;
    const int rowBase = blockIdx.y * 128;
    const int colBase = blockIdx.x * 128;

    // loader: each thread owns one row + 16-k half of the 128x32 stage tile
    const int lrow = tid >> 1;          // 0..127
    const int kh   = tid & 1;           // 0/1 -> k offset 16*kh
    const float* Ap = A  + (long)(rowBase + lrow) * K + 16 * kh;
    const float* Bp = Bm + (long)(colBase + lrow) * K + 16 * kh;

    float acc[4][4][4];
#pragma unroll
    for (int i = 0; i < 4; i++)
#pragma unroll
        for (int j = 0; j < 4; j++)
#pragma unroll
            for (int r = 0; r < 4; r++) acc[i][j][r] = 0.f;

    float4 ra[4], rb[4];

    // split 16 floats (ra or rb) into interleaved hi/lo words and store
    auto store_half = [&](const float4* rv, uint32_t* hiP, uint32_t* loP) {
        uint32_t Wh[8], Wl[8];
#pragma unroll
        for (int j = 0; j < 4; j++) {
            split_pair(rv[j].x, rv[j].y, Wh[2 * j],     Wl[2 * j]);
            split_pair(rv[j].z, rv[j].w, Wh[2 * j + 1], Wl[2 * j + 1]);
        }
        uint32_t* ph = hiP + lrow * SROW + 8 * kh;
        uint32_t* pl = loP + lrow * SROW + 8 * kh;
        // interleave: positions {0..7} <- words {0,4,1,5,2,6,3,7}
        *(uint4*)ph       = make_uint4(Wh[0], Wh[4], Wh[1], Wh[5]);
        *(uint4*)(ph + 4) = make_uint4(Wh[2], Wh[6], Wh[3], Wh[7]);
        *(uint4*)pl       = make_uint4(Wl[0], Wl[4], Wl[1], Wl[5]);
        *(uint4*)(pl + 4) = make_uint4(Wl[2], Wl[6], Wl[3], Wl[7]);
    };

    // preload stage 0 into buffer 0
#pragma unroll
    for (int j = 0; j < 4; j++) {
        ra[j] = *(const float4*)(Ap + 4 * j);
        rb[j] = *(const float4*)(Bp + 4 * j);
    }
    store_half(ra, sm, sm + PLANE_W);
    store_half(rb, sm + 2 * PLANE_W, sm + 3 * PLANE_W);
    __syncthreads();

    const int NS = K / 32;
    for (int s = 0; s < NS; s++) {
        const int b = s & 1;
        uint32_t* base = sm + b * STAGE_W;

        // prefetch next stage (LDG in flight during mma)
        if (s + 1 < NS) {
            const float* ap = Ap + (s + 1) * 32;
            const float* bp = Bp + (s + 1) * 32;
#pragma unroll
            for (int j = 0; j < 4; j++) {
                ra[j] = *(const float4*)(ap + 4 * j);
                rb[j] = *(const float4*)(bp + 4 * j);
            }
        }

        // mma over the 2 k16 steps of this stage
#pragma unroll
        for (int kk = 0; kk < 2; kk++) {
            uint32_t af[4][2][4];
#pragma unroll
            for (int mi = 0; mi < 4; mi++) {
                const int r0 = wr * 64 + mi * 16 + gid;
#pragma unroll
                for (int h = 0; h < 2; h++) {
                    const uint32_t* pl = base + h * PLANE_W;
                    uint2 u = *(const uint2*)(pl + r0 * SROW + kk * 8 + 2 * tig);
                    uint2 w = *(const uint2*)(pl + (r0 + 8) * SROW + kk * 8 + 2 * tig);
                    af[mi][h][0] = u.x;  // a0: row g,   k-chunk0
                    af[mi][h][1] = w.x;  // a1: row g+8, chunk0
                    af[mi][h][2] = u.y;  // a2: row g,   chunk1
                    af[mi][h][3] = w.y;  // a3: row g+8, chunk1
                }
            }
            uint32_t bfr[4][2][2];
#pragma unroll
            for (int ni = 0; ni < 4; ni++) {
                const int c0 = wc * 32 + ni * 8 + gid;
#pragma unroll
                for (int h = 0; h < 2; h++) {
                    const uint32_t* pl = base + (2 + h) * PLANE_W;
                    uint2 v = *(const uint2*)(pl + c0 * SROW + kk * 8 + 2 * tig);
                    bfr[ni][h][0] = v.x;
                    bfr[ni][h][1] = v.y;
                }
            }
#pragma unroll
            for (int mi = 0; mi < 4; mi++)
#pragma unroll
                for (int ni = 0; ni < 4; ni++) {
                    mma_bf16(acc[mi][ni], af[mi][0], bfr[ni][0]);  // hh
                    mma_bf16(acc[mi][ni], af[mi][0], bfr[ni][1]);  // hl
                    mma_bf16(acc[mi][ni], af[mi][1], bfr[ni][0]);  // lh
                }
        }

        // split + store next stage into the other buffer
        if (s + 1 < NS) {
            uint32_t* nb = sm + (1 - b) * STAGE_W;
            store_half(ra, nb, nb + PLANE_W);
            store_half(rb, nb + 2 * PLANE_W, nb + 3 * PLANE_W);
        }
        __syncthreads();
    }

    // epilogue
#pragma unroll
    for (int mi = 0; mi < 4; mi++) {
        const int r = rowBase + wr * 64 + mi * 16 + gid;
#pragma unroll
        for (int ni = 0; ni < 4; ni++) {
            const int cc = colBase + wc * 32 + ni * 8 + 2 * tig;
            float2 v0 = make_float2(acc[mi][ni][0] * alpha, acc[mi][ni][1] * alpha);
            float2 v1 = make_float2(acc[mi][ni][2] * alpha, acc[mi][ni][3] * alpha);
            *(float2*)(C + (long)r * Nn + cc)       = v0;
            *(float2*)(C + (long)(r + 8) * Nn + cc) = v1;
        }
    }
}

// ---------------------------------------------------------------------------
// Transpose vp [B][SEQ][EMB] -> vpt [B][EMB][SEQ]
// ---------------------------------------------------------------------------
__global__ void __launch_bounds__(256) transpose_k(
    const float* __restrict__ src, float* __restrict__ dst)
{
    __shared__ float t[32][33];
    const int b = blockIdx.z;
    const int n0 = blockIdx.x * 32, e0 = blockIdx.y * 32;
    const float* s = src + (long)b * SEQ * EMB;
    float* d = dst + (long)b * SEQ * EMB;
    const int x = threadIdx.x, y = threadIdx.y;  // 32 x 8
#pragma unroll
    for (int dy = 0; dy < 32; dy += 8)
        t[y + dy][x] = s[(long)(n0 + y + dy) * EMB + e0 + x];
    __syncthreads();
#pragma unroll
    for (int dy = 0; dy < 32; dy += 8)
        d[(long)(e0 + y + dy) * SEQ + n0 + x] = t[x][y + dy];
}

// ---------------------------------------------------------------------------
// Row softmax (in place)
// ---------------------------------------------------------------------------
__global__ void __launch_bounds__(256) softmax_rows(float* __restrict__ attn)
{
    float* p = attn + (long)blockIdx.x * SEQ;
    const int tid = threadIdx.x;
    __shared__ float red[256];

    float vals[8];
    float lmax = -INFINITY;
#pragma unroll
    for (int i = 0; i < 8; i++) {
        vals[i] = p[tid + i * 256];
        lmax = fmaxf(lmax, vals[i]);
    }
    red[tid] = lmax;
    __syncthreads();
    for (int s = 128; s > 0; s >>= 1) {
        if (tid < s) red[tid] = fmaxf(red[tid], red[tid + s]);
        __syncthreads();
    }
    const float m = red[0];
    __syncthreads();

    float lsum = 0.f;
#pragma unroll
    for (int i = 0; i < 8; i++) {
        vals[i] = __expf(vals[i] - m);
        lsum += vals[i];
    }
    red[tid] = lsum;
    __syncthreads();
    for (int s = 128; s > 0; s >>= 1) {
        if (tid < s) red[tid] += red[tid + s];
        __syncthreads();
    }
    const float inv = 1.f / red[0];
#pragma unroll
    for (int i = 0; i < 8; i++)
        p[tid + i * 256] = vals[i] * inv;
}

// ---------------------------------------------------------------------------
extern "C" void kernel_launch(void* const* d_in, const int* in_sizes, int n_in,
                              void* d_out, int out_size)
{
    const float* q  = (const float*)d_in[0];
    const float* k  = (const float*)d_in[1];
    const float* v  = (const float*)d_in[2];
    const float* Wq = (const float*)d_in[3];
    const float* Wk = (const float*)d_in[4];
    const float* Wv = (const float*)d_in[5];

    float* out  = (float*)d_out;                  // [B, N, E]
    float* attn = out + (long)BATCH * SEQ * EMB;  // [B, N, N]

    float *qp, *kp, *vp, *vpt;
    cudaGetSymbolAddress((void**)&qp,  g_qp);
    cudaGetSymbolAddress((void**)&kp,  g_kp);
    cudaGetSymbolAddress((void**)&vp,  g_vp);
    cudaGetSymbolAddress((void**)&vpt, g_vpt);

    cudaFuncSetAttribute(gemm_bf3, cudaFuncAttributeMaxDynamicSharedMemorySize,
                         SMEM_BYTES);

    const float c = 0.044194173824159216f;  // 1/sqrt(512)

    // Projections: M = B*N folded, N = EMB, K = DIM
    dim3 gp(EMB / 128, (BATCH * SEQ) / 128, 1);
    gemm_bf3<<<gp, 256, SMEM_BYTES>>>(q, Wq, qp, BATCH * SEQ, EMB, DIM, c, 0, 0, 0);
    gemm_bf3<<<gp, 256, SMEM_BYTES>>>(k, Wk, kp, BATCH * SEQ, EMB, DIM, c, 0, 0, 0);
    gemm_bf3<<<gp, 256, SMEM_BYTES>>>(v, Wv, vp, BATCH * SEQ, EMB, DIM, c, 0, 0, 0);

    // vp -> vpt so the out-GEMM is NT (B K-major)
    dim3 gt(SEQ / 32, EMB / 32, BATCH);
    transpose_k<<<gt, dim3(32, 8)>>>(vp, vpt);

    // dots = qp @ kp^T * c
    dim3 gd(SEQ / 128, SEQ / 128, BATCH);
    gemm_bf3<<<gd, 256, SMEM_BYTES>>>(qp, kp, attn, SEQ, SEQ, EMB, c,
                                      (long)SEQ * EMB, (long)SEQ * EMB,
                                      (long)SEQ * SEQ);

    softmax_rows<<<BATCH * SEQ, 256>>>(attn);

    // out = attn @ vpt^T
    dim3 go(EMB / 128, SEQ / 128, BATCH);
    gemm_bf3<<<go, 256, SMEM_BYTES>>>(attn, vpt, out, SEQ, EMB, SEQ, 1.0f,
                                      (long)SEQ * SEQ, (long)SEQ * EMB,
                                      (long)SEQ * EMB);
}